// round 3
// baseline (speedup 1.0000x reference)
#include <cuda_runtime.h>
#include <math.h>

#define BB 2
#define C 19
#define H 128
#define W 128
#define HW (H*W)          // 16384
#define CF 256
#define SH 64
#define SW 64
#define SP (SH*SW)        // 4096
#define N2 (BB*SP)        // 8192

#define TW 16             // main-kernel tile width
#define TH 8              // main-kernel tile height
#define NBLK ((W/TW)*(H/TH)*BB)   // 256
#define HALO_W (TW+2)     // 18
#define HALO_N (HALO_W*(TH+2))    // 180

// Scratch (static device globals; no allocations)
__device__ float  g_prob[BB*C*HW];     // softmax probs [b][c][h][w]
__device__ float  g_spart[20*N2];      // [split*5+dir][b*SP+s], dir: 0=self 1=E 2=SW 3=S 4=SE
__device__ float  g_sim[9*N2];         // [k][b*SP+s]
__device__ double g_partial[3*NBLK];

// ---------------- K1: softmax over 19 channels ----------------
__global__ void k_softmax(const float* __restrict__ logits) {
    int idx = blockIdx.x * blockDim.x + threadIdx.x;   // over B*H*W
    if (idx >= BB*HW) return;
    int b = idx >> 14;
    int p = idx & (HW - 1);
    const float* x = logits + (size_t)b * C * HW + p;
    float v[C];
    float m = -1e30f;
    #pragma unroll
    for (int c = 0; c < C; c++) { v[c] = x[(size_t)c * HW]; m = fmaxf(m, v[c]); }
    float s = 0.f;
    #pragma unroll
    for (int c = 0; c < C; c++) { v[c] = expf(v[c] - m); s += v[c]; }
    float inv = 1.f / s;
    float* o = g_prob + (size_t)b * C * HW + p;
    #pragma unroll
    for (int c = 0; c < C; c++) o[(size_t)c * HW] = v[c] * inv;
}

// ------- K2: channel-split stencil partial distances (native layout) -------
// grid (16 row-tiles, 4 channel-splits, BB); block 256 = 4 rows x 64 cols
__global__ void k_simpart(const float* __restrict__ feats) {
    __shared__ float tf[16][5][66];
    int b     = blockIdx.z;
    int split = blockIdx.y;
    int r0    = blockIdx.x * 4;
    int tid = threadIdx.x;
    int r = tid >> 6, cc = tid & 63;
    const float* fb = feats + ((size_t)b * CF + split * 64) * SP;

    float a0 = 0.f, a1 = 0.f, a2 = 0.f, a3 = 0.f, a4 = 0.f;
    for (int c0 = 0; c0 < 64; c0 += 16) {
        __syncthreads();
        for (int j = tid; j < 16*5*66; j += 256) {
            int ch  = j / 330;
            int rem = j - ch * 330;
            int rr  = rem / 66;
            int col = rem - rr * 66;
            int gr = r0 + rr, gc = col - 1;
            float v = 0.f;
            if (gr < SH && gc >= 0 && gc < SW)
                v = fb[(size_t)(c0 + ch) * SP + gr * SW + gc];
            tf[ch][rr][col] = v;
        }
        __syncthreads();
        #pragma unroll
        for (int ch = 0; ch < 16; ch++) {
            float f   = tf[ch][r][cc + 1];
            float fe  = tf[ch][r][cc + 2];
            float fsw = tf[ch][r + 1][cc];
            float fs  = tf[ch][r + 1][cc + 1];
            float fse = tf[ch][r + 1][cc + 2];
            a0 += f * f;
            float d;
            d = f - fe;  a1 += d * d;
            d = f - fsw; a2 += d * d;
            d = f - fs;  a3 += d * d;
            d = f - fse; a4 += d * d;
        }
    }
    size_t base = (size_t)b * SP + (r0 + r) * SW + cc;
    g_spart[(split*5 + 0) * N2 + base] = a0;
    g_spart[(split*5 + 1) * N2 + base] = a1;
    g_spart[(split*5 + 2) * N2 + base] = a2;
    g_spart[(split*5 + 3) * N2 + base] = a3;
    g_spart[(split*5 + 4) * N2 + base] = a4;
}

// ------- K3: combine splits, derive backward dirs by symmetry, exp --------
__global__ void k_simfin() {
    int idx = blockIdx.x * blockDim.x + threadIdx.x;   // b*SP+s
    if (idx >= N2) return;
    int s  = idx & (SP - 1);
    int sh = s >> 6, sw = s & 63;

    float self = 0.f, fE = 0.f, fSW = 0.f, fS = 0.f, fSE = 0.f;
    #pragma unroll
    for (int sp = 0; sp < 4; sp++) {
        self += g_spart[(sp*5 + 0) * N2 + idx];
        fE   += g_spart[(sp*5 + 1) * N2 + idx];
        fSW  += g_spart[(sp*5 + 2) * N2 + idx];
        fS   += g_spart[(sp*5 + 3) * N2 + idx];
        fSE  += g_spart[(sp*5 + 4) * N2 + idx];
    }
    bool wOK = (sw > 0), eOK = (sw < SW-1), nOK = (sh > 0), sOK = (sh < SH-1);

    float bW = 0.f, bNE = 0.f, bN = 0.f, bNW = 0.f;
    #pragma unroll
    for (int sp = 0; sp < 4; sp++) {
        if (wOK)         bW  += g_spart[(sp*5 + 1) * N2 + idx - 1];       // E of s-1
        if (nOK && eOK)  bNE += g_spart[(sp*5 + 2) * N2 + idx - SW + 1];  // SW of s-63
        if (nOK)         bN  += g_spart[(sp*5 + 3) * N2 + idx - SW];      // S of s-64
        if (nOK && wOK)  bNW += g_spart[(sp*5 + 4) * N2 + idx - SW - 1];  // SE of s-65
    }
    g_sim[4*N2 + idx] = expf(-self);
    g_sim[5*N2 + idx] = eOK          ? expf(-fE)  : 0.f;
    g_sim[6*N2 + idx] = (sOK && wOK) ? expf(-fSW) : 0.f;
    g_sim[7*N2 + idx] = sOK          ? expf(-fS)  : 0.f;
    g_sim[8*N2 + idx] = (sOK && eOK) ? expf(-fSE) : 0.f;
    g_sim[3*N2 + idx] = wOK          ? expf(-bW)  : 0.f;
    g_sim[2*N2 + idx] = (nOK && eOK) ? expf(-bNE) : 0.f;
    g_sim[1*N2 + idx] = nOK          ? expf(-bN)  : 0.f;
    g_sim[0*N2 + idx] = (nOK && wOK) ? expf(-bNW) : 0.f;
}

// ---------------- K4: per-pixel main (shared prob halo) ----------------
__global__ void k_main(const float* __restrict__ ori, float* __restrict__ out) {
    __shared__ float sp[C * HALO_N];
    __shared__ float rp[128], rn[128], rc[128];

    int tid = threadIdx.x;                    // 0..127
    int b   = blockIdx.z;
    int h0  = blockIdx.y * TH;
    int w0  = blockIdx.x * TW;
    int bid = (blockIdx.z * (H/TH) + blockIdx.y) * (W/TW) + blockIdx.x;

    const float* pb = g_prob + (size_t)b * C * HW;
    for (int j = tid; j < C * HALO_N; j += 128) {
        int c   = j / HALO_N;
        int rem = j - c * HALO_N;
        int rr  = rem / HALO_W;
        int col = rem - rr * HALO_W;
        int gh = h0 - 1 + rr, gw = w0 - 1 + col;
        float v = 0.f;
        if (gh >= 0 && gh < H && gw >= 0 && gw < W)
            v = pb[(size_t)c * HW + gh * W + gw];
        sp[j] = v;
    }
    __syncthreads();

    int lr = tid >> 4, lc = tid & 15;
    int h = h0 + lr, w = w0 + lc;
    int p = h * W + w;
    int sh2 = h >> 1, sw2 = w >> 1;
    size_t sbase = (size_t)b * SP + sh2 * SW + sw2;

    int cbase = (lr + 1) * HALO_W + (lc + 1);
    float pc[C];
    float sump = 0.f;
    #pragma unroll
    for (int c = 0; c < C; c++) { pc[c] = sp[c * HALO_N + cbase]; sump += pc[c]; }

    float simC = g_sim[4*N2 + sbase];   // self-norm sim (for padded neighbors)
    float sim[9], pos[9], neg[9];

    #pragma unroll
    for (int k = 0; k < 9; k++) {
        int dr = k / 3 - 1, dc = k % 3 - 1;
        int hn = h + dr, wn = w + dc;
        bool valid = (hn >= 0 && hn < H && wn >= 0 && wn < W);
        int nidx = cbase + dr * HALO_W + dc;
        float d = 0.f;
        #pragma unroll
        for (int c = 0; c < C; c++) d += pc[c] * sp[c * HALO_N + nidx];
        pos[k] = d;
        neg[k] = valid ? (sump - d) : -d;   // sump*sumq - pos, sumq in {~1, 0}
        if (!valid) {
            sim[k] = simC;
        } else {
            int dsh = (hn >> 1) - sh2, dsw = (wn >> 1) - sw2;
            int ks = (dsh + 1) * 3 + (dsw + 1);
            sim[k] = (ks == 4) ? 1.0f : g_sim[ks * N2 + sbase];
        }
    }

    float ssum = 0.f;
    #pragma unroll
    for (int k = 0; k < 9; k++) ssum += sim[k];
    out[2 + b * HW + p] = ssum * (1.f / 9.f);

    // top-5 by sim descending, stable ties (lower index first)
    bool used[9];
    #pragma unroll
    for (int k = 0; k < 9; k++) used[k] = false;
    float lp = 0.f;
    #pragma unroll
    for (int t = 0; t < 5; t++) {
        int bi = 0; float bv = -1e30f;
        #pragma unroll
        for (int k = 0; k < 9; k++)
            if (!used[k] && sim[k] > bv) { bv = sim[k]; bi = k; }
        used[bi] = true;
        lp += bv * (-pos[bi]);
    }
    // bottom-4 by sim ascending, stable ties
    bool used2[9];
    #pragma unroll
    for (int k = 0; k < 9; k++) used2[k] = false;
    float ln = 0.f;
    #pragma unroll
    for (int t = 0; t < 4; t++) {
        int bi = 0; float bv = 1e30f;
        #pragma unroll
        for (int k = 0; k < 9; k++)
            if (!used2[k] && sim[k] < bv) { bv = sim[k]; bi = k; }
        used2[bi] = true;
        ln += (1.f - bv) * (-neg[bi]);
    }

    float f0  = ori[(size_t)b * CF * SP + sh2 * SW + sw2];
    float msk = (f0 > 0.f) ? 1.f : 0.f;

    rp[tid] = msk * lp; rn[tid] = msk * ln; rc[tid] = msk;
    __syncthreads();
    #pragma unroll
    for (int o = 64; o > 0; o >>= 1) {
        if (tid < o) {
            rp[tid] += rp[tid + o];
            rn[tid] += rn[tid + o];
            rc[tid] += rc[tid + o];
        }
        __syncthreads();
    }
    if (tid == 0) {
        g_partial[bid]            = (double)rp[0];
        g_partial[NBLK + bid]     = (double)rn[0];
        g_partial[2 * NBLK + bid] = (double)rc[0];
    }
}

// ---------------- K5: final deterministic reduction ----------------
__global__ void k_final(float* __restrict__ out) {
    __shared__ double dp[NBLK], dn[NBLK], dc[NBLK];
    int t = threadIdx.x;
    dp[t] = g_partial[t];
    dn[t] = g_partial[NBLK + t];
    dc[t] = g_partial[2 * NBLK + t];
    __syncthreads();
    #pragma unroll
    for (int o = NBLK/2; o > 0; o >>= 1) {
        if (t < o) { dp[t] += dp[t + o]; dn[t] += dn[t + o]; dc[t] += dc[t + o]; }
        __syncthreads();
    }
    if (t == 0) {
        double cnt = dc[0];
        out[0] = (float)(dp[0] / (cnt * 5.0));   // /(cnt*(TOP_K+1)) * W_POS
        out[1] = (float)(dn[0] / (cnt * 4.0));   // /(cnt*TOP_K)     * W_NEG
    }
}

extern "C" void kernel_launch(void* const* d_in, const int* in_sizes, int n_in,
                              void* d_out, int out_size) {
    const float* ori;
    const float* logits;
    if (in_sizes[0] == BB * CF * SP) {
        ori    = (const float*)d_in[0];
        logits = (const float*)d_in[1];
    } else {
        ori    = (const float*)d_in[1];
        logits = (const float*)d_in[0];
    }
    float* out = (float*)d_out;

    k_softmax<<<256, 128>>>(logits);
    dim3 sgrid(16, 4, BB);
    k_simpart<<<sgrid, 256>>>(ori);
    k_simfin<<<N2 / 256, 256>>>();
    dim3 mgrid(W / TW, H / TH, BB);
    k_main<<<mgrid, 128>>>(ori, out);
    k_final<<<1, NBLK>>>(out);
}

// round 4
// speedup vs baseline: 1.6360x; 1.6360x over previous
#include <cuda_runtime.h>
#include <math.h>

#define BB 2
#define C 19
#define CP 20             // padded channels
#define H 128
#define W 128
#define HW (H*W)          // 16384
#define CF 256
#define SH 64
#define SW 64
#define SP (SH*SW)        // 4096
#define N2 (BB*SP)        // 8192
#define NCHUNK 8          // feature channel chunks of 32
#define NBLK 128          // main-kernel blocks

// Scratch (static device globals; no allocations)
__device__ float  g_prob2[BB*HW*CP];     // padded probs [b*HW+p][20], [19]=0
__device__ float  g_spart[NCHUNK*5*N2];  // [chunk*5+dir][b*SP+s]; dir 0=self 1=E 2=SW 3=S 4=SE
__device__ float  g_sim[9*N2];           // [k][b*SP+s]
__device__ double g_partial[3*NBLK];
__device__ int    g_count = 0;

// ---------------- K1: softmax -> padded [pixel][20] layout ----------------
__global__ void k_softmax(const float* __restrict__ logits) {
    int idx = blockIdx.x * blockDim.x + threadIdx.x;   // over B*H*W
    if (idx >= BB*HW) return;
    int b = idx >> 14;
    int p = idx & (HW - 1);
    const float* x = logits + (size_t)b * C * HW + p;
    float v[CP];
    float m = -1e30f;
    #pragma unroll
    for (int c = 0; c < C; c++) { v[c] = x[(size_t)c * HW]; m = fmaxf(m, v[c]); }
    float s = 0.f;
    #pragma unroll
    for (int c = 0; c < C; c++) { v[c] = expf(v[c] - m); s += v[c]; }
    float inv = 1.f / s;
    #pragma unroll
    for (int c = 0; c < C; c++) v[c] *= inv;
    v[19] = 0.f;
    float4* o = reinterpret_cast<float4*>(g_prob2 + (size_t)idx * CP);
    #pragma unroll
    for (int q = 0; q < 5; q++)
        o[q] = make_float4(v[4*q], v[4*q+1], v[4*q+2], v[4*q+3]);
}

// ------- K2: per-(source,32ch-chunk) stencil partial distances -------
__global__ void k_simpart(const float* __restrict__ feats) {
    int idx   = blockIdx.x * blockDim.x + threadIdx.x;   // b*SP+s
    int chunk = blockIdx.y;
    int b  = idx >> 12;
    int s  = idx & (SP - 1);
    int sh = s >> 6, sw = s & 63;

    // forward-neighbor offsets; 0 (self) when OOB -> partial=0, masked later
    bool eOK = (sw < SW-1), sOK = (sh < SH-1), wOK = (sw > 0);
    int dE  = eOK ? 1 : 0;
    int dSW = (sOK && wOK) ? (SW - 1) : 0;
    int dS  = sOK ? SW : 0;
    int dSE = (sOK && eOK) ? (SW + 1) : 0;

    const float* fb = feats + ((size_t)b * CF + chunk * 32) * SP + s;
    float a0 = 0.f, a1 = 0.f, a2 = 0.f, a3 = 0.f, a4 = 0.f;
    #pragma unroll
    for (int ch = 0; ch < 32; ch++) {
        const float* fp = fb + (size_t)ch * SP;
        float f = fp[0];
        float d;
        a0 += f * f;
        d = f - fp[dE];  a1 += d * d;
        d = f - fp[dSW]; a2 += d * d;
        d = f - fp[dS];  a3 += d * d;
        d = f - fp[dSE]; a4 += d * d;
    }
    g_spart[(chunk*5 + 0) * N2 + idx] = a0;
    g_spart[(chunk*5 + 1) * N2 + idx] = a1;
    g_spart[(chunk*5 + 2) * N2 + idx] = a2;
    g_spart[(chunk*5 + 3) * N2 + idx] = a3;
    g_spart[(chunk*5 + 4) * N2 + idx] = a4;
}

// ------- K3: combine chunks, derive backward dirs by symmetry, exp --------
__global__ void k_simfin() {
    int idx = blockIdx.x * blockDim.x + threadIdx.x;   // b*SP+s
    if (idx >= N2) return;
    int s  = idx & (SP - 1);
    int sh = s >> 6, sw = s & 63;

    float self = 0.f, fE = 0.f, fSW = 0.f, fS = 0.f, fSE = 0.f;
    #pragma unroll
    for (int cu = 0; cu < NCHUNK; cu++) {
        self += g_spart[(cu*5 + 0) * N2 + idx];
        fE   += g_spart[(cu*5 + 1) * N2 + idx];
        fSW  += g_spart[(cu*5 + 2) * N2 + idx];
        fS   += g_spart[(cu*5 + 3) * N2 + idx];
        fSE  += g_spart[(cu*5 + 4) * N2 + idx];
    }
    bool wOK = (sw > 0), eOK = (sw < SW-1), nOK = (sh > 0), sOK = (sh < SH-1);

    float bW = 0.f, bNE = 0.f, bN = 0.f, bNW = 0.f;
    #pragma unroll
    for (int cu = 0; cu < NCHUNK; cu++) {
        if (wOK)         bW  += g_spart[(cu*5 + 1) * N2 + idx - 1];       // E of s-1
        if (nOK && eOK)  bNE += g_spart[(cu*5 + 2) * N2 + idx - SW + 1];  // SW of s-63
        if (nOK)         bN  += g_spart[(cu*5 + 3) * N2 + idx - SW];      // S of s-64
        if (nOK && wOK)  bNW += g_spart[(cu*5 + 4) * N2 + idx - SW - 1];  // SE of s-65
    }
    g_sim[4*N2 + idx] = expf(-self);
    g_sim[5*N2 + idx] = eOK          ? expf(-fE)  : 0.f;
    g_sim[6*N2 + idx] = (sOK && wOK) ? expf(-fSW) : 0.f;
    g_sim[7*N2 + idx] = sOK          ? expf(-fS)  : 0.f;
    g_sim[8*N2 + idx] = (sOK && eOK) ? expf(-fSE) : 0.f;
    g_sim[3*N2 + idx] = wOK          ? expf(-bW)  : 0.f;
    g_sim[2*N2 + idx] = (nOK && eOK) ? expf(-bNE) : 0.f;
    g_sim[1*N2 + idx] = nOK          ? expf(-bN)  : 0.f;
    g_sim[0*N2 + idx] = (nOK && wOK) ? expf(-bNW) : 0.f;
}

// ---------------- K4: per-pixel main + fused final ----------------
__global__ void k_main(const float* __restrict__ ori, float* __restrict__ out) {
    __shared__ float rp[256], rn[256], rc[256];
    __shared__ int   sh_last;

    int tid = threadIdx.x;
    int idx = blockIdx.x * 256 + tid;          // b*HW+p, 0..32767
    int b = idx >> 14;
    int p = idx & (HW - 1);
    int h = p >> 7, w = p & 127;
    int sh2 = h >> 1, sw2 = w >> 1;
    size_t sbase = (size_t)b * SP + sh2 * SW + sw2;

    const float4* cen = reinterpret_cast<const float4*>(g_prob2 + (size_t)idx * CP);
    float4 pc[5];
    #pragma unroll
    for (int q = 0; q < 5; q++) pc[q] = cen[q];
    float sump = 0.f;
    #pragma unroll
    for (int q = 0; q < 5; q++) sump += pc[q].x + pc[q].y + pc[q].z + pc[q].w;

    float simC = g_sim[4*N2 + sbase];
    float sim[9], pos[9], neg[9];

    #pragma unroll
    for (int k = 0; k < 9; k++) {
        int dr = k / 3 - 1, dc = k % 3 - 1;
        int hn = h + dr, wn = w + dc;
        bool valid = (hn >= 0 && hn < H && wn >= 0 && wn < W);
        float d = 0.f;
        if (valid) {
            const float4* qv = reinterpret_cast<const float4*>(
                g_prob2 + ((size_t)b * HW + hn * W + wn) * CP);
            #pragma unroll
            for (int q = 0; q < 5; q++) {
                float4 qq = qv[q];
                d += pc[q].x * qq.x + pc[q].y * qq.y + pc[q].z * qq.z + pc[q].w * qq.w;
            }
            pos[k] = d;
            neg[k] = sump - d;       // sumq == 1 for valid neighbors
            int dsh = (hn >> 1) - sh2, dsw = (wn >> 1) - sw2;
            int ks = (dsh + 1) * 3 + (dsw + 1);
            sim[k] = (ks == 4) ? 1.0f : g_sim[ks * N2 + sbase];
        } else {
            pos[k] = 0.f;
            neg[k] = 0.f;
            sim[k] = simC;
        }
    }

    float ssum = 0.f;
    #pragma unroll
    for (int k = 0; k < 9; k++) ssum += sim[k];
    out[2 + idx] = ssum * (1.f / 9.f);

    // top-5 by sim descending, stable ties (lower index first)
    bool used[9];
    #pragma unroll
    for (int k = 0; k < 9; k++) used[k] = false;
    float lp = 0.f;
    #pragma unroll
    for (int t = 0; t < 5; t++) {
        int bi = 0; float bv = -1e30f;
        #pragma unroll
        for (int k = 0; k < 9; k++)
            if (!used[k] && sim[k] > bv) { bv = sim[k]; bi = k; }
        used[bi] = true;
        lp += bv * (-pos[bi]);
    }
    // bottom-4 by sim ascending, stable ties
    bool used2[9];
    #pragma unroll
    for (int k = 0; k < 9; k++) used2[k] = false;
    float ln = 0.f;
    #pragma unroll
    for (int t = 0; t < 4; t++) {
        int bi = 0; float bv = 1e30f;
        #pragma unroll
        for (int k = 0; k < 9; k++)
            if (!used2[k] && sim[k] < bv) { bv = sim[k]; bi = k; }
        used2[bi] = true;
        ln += (1.f - bv) * (-neg[bi]);
    }

    float f0  = ori[(size_t)b * CF * SP + sh2 * SW + sw2];
    float msk = (f0 > 0.f) ? 1.f : 0.f;

    rp[tid] = msk * lp; rn[tid] = msk * ln; rc[tid] = msk;
    __syncthreads();
    #pragma unroll
    for (int o = 128; o > 0; o >>= 1) {
        if (tid < o) {
            rp[tid] += rp[tid + o];
            rn[tid] += rn[tid + o];
            rc[tid] += rc[tid + o];
        }
        __syncthreads();
    }
    if (tid == 0) {
        g_partial[blockIdx.x]            = (double)rp[0];
        g_partial[NBLK + blockIdx.x]     = (double)rn[0];
        g_partial[2 * NBLK + blockIdx.x] = (double)rc[0];
        __threadfence();
        int v = atomicAdd(&g_count, 1);
        sh_last = (v == NBLK - 1) ? 1 : 0;
    }
    __syncthreads();

    if (sh_last) {
        __shared__ double dp[128], dn[128], dc2[128];
        if (tid < 128) {
            volatile double* gp = g_partial;
            dp[tid]  = gp[tid];
            dn[tid]  = gp[NBLK + tid];
            dc2[tid] = gp[2 * NBLK + tid];
        }
        __syncthreads();
        #pragma unroll
        for (int o = 64; o > 0; o >>= 1) {
            if (tid < o) { dp[tid] += dp[tid + o]; dn[tid] += dn[tid + o]; dc2[tid] += dc2[tid + o]; }
            __syncthreads();
        }
        if (tid == 0) {
            double cnt = dc2[0];
            out[0] = (float)(dp[0] / (cnt * 5.0));   // /(cnt*(TOP_K+1)) * W_POS
            out[1] = (float)(dn[0] / (cnt * 4.0));   // /(cnt*TOP_K)     * W_NEG
            g_count = 0;                              // reset for graph replay
        }
    }
}

extern "C" void kernel_launch(void* const* d_in, const int* in_sizes, int n_in,
                              void* d_out, int out_size) {
    const float* ori;
    const float* logits;
    if (in_sizes[0] == BB * CF * SP) {
        ori    = (const float*)d_in[0];
        logits = (const float*)d_in[1];
    } else {
        ori    = (const float*)d_in[1];
        logits = (const float*)d_in[0];
    }
    float* out = (float*)d_out;

    k_softmax<<<128, 256>>>(logits);
    dim3 sgrid(N2 / 256, NCHUNK);
    k_simpart<<<sgrid, 256>>>(ori);
    k_simfin<<<N2 / 256, 256>>>();
    k_main<<<NBLK, 256>>>(ori, out);
}